// round 1
// baseline (speedup 1.0000x reference)
#include <cuda_runtime.h>
#include <math_constants.h>

#define BB 4
#define NN 2048
#define CC 320
#define HH 5
#define DD 64
#define GG (BB*HH)      // 20
#define ROWS (BB*NN)    // 8192

// scratch (allocation-free rule: __device__ globals)
__device__ float g_q[GG*NN*DD];
__device__ float g_k[GG*NN*DD];
__device__ float g_v[GG*NN*DD];
__device__ float g_attn[GG*NN*DD];

// ---------------------------------------------------------------------------
// Kernel 1: fused QKV projection.
// x:(8192,320) @ W:(320,320) for Wq/Wk/Wv, output in (g=b*H+h, n, d) layout.
// grid: (15 col-tiles of 64, 128 row-tiles of 64), 256 threads, 4x4 micro.
// ---------------------------------------------------------------------------
__global__ void qkv_kernel(const float* __restrict__ x,
                           const float* __restrict__ Wq,
                           const float* __restrict__ Wk,
                           const float* __restrict__ Wv)
{
    __shared__ float As[16][68];
    __shared__ float Bs[16][68];

    const int tid = threadIdx.x;
    const int tx = tid & 15, ty = tid >> 4;
    const int row0 = blockIdx.y * 64;
    const int colt = blockIdx.x;            // 0..14
    const int w = colt / 5;                 // 0=q 1=k 2=v
    const int h = colt % 5;                 // head (64-wide tiles align to heads)
    const int wc0 = h * 64;
    const float* __restrict__ W = (w == 0) ? Wq : (w == 1) ? Wk : Wv;

    float acc[4][4] = {};

    for (int k0 = 0; k0 < CC; k0 += 16) {
        // A tile: 64 rows x 16 k, stored transposed As[k][row]
        {
            int kk = tid & 15, r = tid >> 4;
            #pragma unroll
            for (int i = 0; i < 4; i++)
                As[kk][r + 16*i] = x[(row0 + r + 16*i)*CC + k0 + kk];
        }
        // B tile: 16 k x 64 cols
        {
            int c = tid & 63, kk = tid >> 6;
            #pragma unroll
            for (int i = 0; i < 4; i++)
                Bs[kk + 4*i][c] = W[(k0 + kk + 4*i)*CC + wc0 + c];
        }
        __syncthreads();

        #pragma unroll
        for (int kk = 0; kk < 16; kk++) {
            float4 av = *(const float4*)&As[kk][ty*4];
            float4 bv = *(const float4*)&Bs[kk][tx*4];
            float a[4] = {av.x, av.y, av.z, av.w};
            float b[4] = {bv.x, bv.y, bv.z, bv.w};
            #pragma unroll
            for (int i = 0; i < 4; i++)
                #pragma unroll
                for (int j = 0; j < 4; j++)
                    acc[i][j] += a[i] * b[j];
        }
        __syncthreads();
    }

    float* __restrict__ dst = (w == 0) ? g_q : (w == 1) ? g_k : g_v;
    #pragma unroll
    for (int i = 0; i < 4; i++) {
        int row = row0 + ty*4 + i;
        int b = row / NN, n = row % NN;
        float4 o = make_float4(acc[i][0], acc[i][1], acc[i][2], acc[i][3]);
        *(float4*)&dst[((b*HH + h)*NN + n)*DD + tx*4] = o;
    }
}

// ---------------------------------------------------------------------------
// Kernel 2: flash attention with edge weighting.
// s_ij = (q_i . k_j) * scale * e_i * e_j ; softmax over j ; O = P @ V.
// grid: (32 row-tiles of 64, G=20), 256 threads.
// dyn smem: Qs/Ks/Vs/Ss [64][68] + ei/ej/m/l/c [64] = 70912 B.
// NOTE: edge index is g % B (batch-minor repeat in the reference!).
// ---------------------------------------------------------------------------
__global__ void attn_kernel(const float* __restrict__ edge)
{
    extern __shared__ float sm[];
    float* Qs = sm;
    float* Ks = Qs + 64*68;
    float* Vs = Ks + 64*68;
    float* Ss = Vs + 64*68;
    float* ei = Ss + 64*68;
    float* ej = ei + 64;
    float* mrow = ej + 64;
    float* lrow = mrow + 64;
    float* crow = lrow + 64;

    const int g = blockIdx.y;
    const int row0 = blockIdx.x * 64;
    const int tid = threadIdx.x;
    const int tx = tid & 15, ty = tid >> 4;
    const int eb = g % BB;                  // batch-minor edge tiling
    const float scale = 0.125f;             // 1/sqrt(64)

    // load Q tile (64x64) into Qs[row][d] (stride 68)
    {
        int d = tid & 63, r = tid >> 6;     // r in 0..3
        #pragma unroll
        for (int i = 0; i < 16; i += 4) {
            int row = r + i*4 + 0; // unrolled below properly
        }
        #pragma unroll
        for (int i = 0; i < 16; i++) {
            int row = r + 4*i;
            Qs[row*68 + d] = g_q[(g*NN + row0 + row)*DD + d];
        }
    }
    if (tid < 64) {
        ei[tid]   = edge[eb*NN + row0 + tid];
        mrow[tid] = -CUDART_INF_F;
        lrow[tid] = 0.0f;
    }
    __syncthreads();

    float acc[4][4] = {};

    for (int jt = 0; jt < 32; jt++) {
        const int j0 = jt * 64;
        // load K and V tiles
        {
            int d = tid & 63, r = tid >> 6;
            #pragma unroll
            for (int i = 0; i < 16; i++) {
                int row = r + 4*i;
                Ks[row*68 + d] = g_k[(g*NN + j0 + row)*DD + d];
                Vs[row*68 + d] = g_v[(g*NN + j0 + row)*DD + d];
            }
        }
        if (tid < 64) ej[tid] = edge[eb*NN + j0 + tid];
        __syncthreads();

        // S = Q @ K^T  (each thread 4x4)
        float s[4][4] = {};
        #pragma unroll
        for (int d0 = 0; d0 < 64; d0 += 4) {
            float a[4][4], b[4][4];
            #pragma unroll
            for (int i = 0; i < 4; i++) {
                float4 t = *(const float4*)&Qs[(ty*4 + i)*68 + d0];
                a[i][0]=t.x; a[i][1]=t.y; a[i][2]=t.z; a[i][3]=t.w;
            }
            #pragma unroll
            for (int j = 0; j < 4; j++) {
                float4 t = *(const float4*)&Ks[(tx*4 + j)*68 + d0];
                b[j][0]=t.x; b[j][1]=t.y; b[j][2]=t.z; b[j][3]=t.w;
            }
            #pragma unroll
            for (int i = 0; i < 4; i++)
                #pragma unroll
                for (int j = 0; j < 4; j++)
                    #pragma unroll
                    for (int d = 0; d < 4; d++)
                        s[i][j] += a[i][d] * b[j][d];
        }
        // write scaled S to smem: s * scale * e_i * e_j
        #pragma unroll
        for (int i = 0; i < 4; i++) {
            float fi = scale * ei[ty*4 + i];
            #pragma unroll
            for (int j = 0; j < 4; j++)
                Ss[(ty*4 + i)*68 + tx*4 + j] = s[i][j] * fi * ej[tx*4 + j];
        }
        __syncthreads();

        // online softmax per row (threads 0..63)
        if (tid < 64) {
            float m_old = mrow[tid];
            float mx = m_old;
            #pragma unroll 8
            for (int j = 0; j < 64; j++)
                mx = fmaxf(mx, Ss[tid*68 + j]);
            float cf = __expf(m_old - mx);     // 0 if m_old == -inf
            float l = lrow[tid] * cf;
            #pragma unroll 8
            for (int j = 0; j < 64; j++) {
                float p = __expf(Ss[tid*68 + j] - mx);
                Ss[tid*68 + j] = p;
                l += p;
            }
            mrow[tid] = mx;
            lrow[tid] = l;
            crow[tid] = cf;
        }
        __syncthreads();

        // rescale accumulators, then O += P @ V
        #pragma unroll
        for (int i = 0; i < 4; i++) {
            float cf = crow[ty*4 + i];
            #pragma unroll
            for (int j = 0; j < 4; j++)
                acc[i][j] *= cf;
        }
        #pragma unroll
        for (int k0 = 0; k0 < 64; k0 += 4) {
            float p[4][4], vv[4][4];
            #pragma unroll
            for (int i = 0; i < 4; i++) {
                float4 t = *(const float4*)&Ss[(ty*4 + i)*68 + k0];
                p[i][0]=t.x; p[i][1]=t.y; p[i][2]=t.z; p[i][3]=t.w;
            }
            #pragma unroll
            for (int kq = 0; kq < 4; kq++) {
                float4 t = *(const float4*)&Vs[(k0 + kq)*68 + tx*4];
                vv[kq][0]=t.x; vv[kq][1]=t.y; vv[kq][2]=t.z; vv[kq][3]=t.w;
            }
            #pragma unroll
            for (int i = 0; i < 4; i++)
                #pragma unroll
                for (int j = 0; j < 4; j++)
                    #pragma unroll
                    for (int kq = 0; kq < 4; kq++)
                        acc[i][j] += p[i][kq] * vv[kq][j];
        }
        __syncthreads();
    }

    // finalize: divide by l, write (g,n,d)
    #pragma unroll
    for (int i = 0; i < 4; i++) {
        int row = ty*4 + i;
        float inv = 1.0f / lrow[row];
        float4 o = make_float4(acc[i][0]*inv, acc[i][1]*inv,
                               acc[i][2]*inv, acc[i][3]*inv);
        *(float4*)&g_attn[(g*NN + row0 + row)*DD + tx*4] = o;
    }
}

// ---------------------------------------------------------------------------
// Kernel 3: output projection with head-merge gather + bias.
// out(b,n,c) = sum_{h,d} attn[(b*H+h), n, d] * Wo[h*64+d, c] + bo[c]
// grid: (5 col-tiles, 128 row-tiles), 256 threads.
// ---------------------------------------------------------------------------
__global__ void oproj_kernel(const float* __restrict__ Wo,
                             const float* __restrict__ bo,
                             float* __restrict__ out)
{
    __shared__ float As[16][68];
    __shared__ float Bs[16][68];

    const int tid = threadIdx.x;
    const int tx = tid & 15, ty = tid >> 4;
    const int row0 = blockIdx.y * 64;
    const int c0 = blockIdx.x * 64;

    float acc[4][4] = {};

    for (int k0 = 0; k0 < CC; k0 += 16) {
        {
            int kk = tid & 15, r = tid >> 4;
            int k = k0 + kk;
            int h = k >> 6, d = k & 63;
            #pragma unroll
            for (int i = 0; i < 4; i++) {
                int row = row0 + r + 16*i;
                int b = row / NN, n = row % NN;
                As[kk][r + 16*i] = g_attn[((b*HH + h)*NN + n)*DD + d];
            }
        }
        {
            int c = tid & 63, kk = tid >> 6;
            #pragma unroll
            for (int i = 0; i < 4; i++)
                Bs[kk + 4*i][c] = Wo[(k0 + kk + 4*i)*CC + c0 + c];
        }
        __syncthreads();

        #pragma unroll
        for (int kk = 0; kk < 16; kk++) {
            float4 av = *(const float4*)&As[kk][ty*4];
            float4 bv = *(const float4*)&Bs[kk][tx*4];
            float a[4] = {av.x, av.y, av.z, av.w};
            float b[4] = {bv.x, bv.y, bv.z, bv.w};
            #pragma unroll
            for (int i = 0; i < 4; i++)
                #pragma unroll
                for (int j = 0; j < 4; j++)
                    acc[i][j] += a[i] * b[j];
        }
        __syncthreads();
    }

    #pragma unroll
    for (int i = 0; i < 4; i++) {
        int row = row0 + ty*4 + i;
        float4 bv = *(const float4*)&bo[c0 + tx*4];
        float4 o = make_float4(acc[i][0] + bv.x, acc[i][1] + bv.y,
                               acc[i][2] + bv.z, acc[i][3] + bv.w);
        *(float4*)&out[row*CC + c0 + tx*4] = o;
    }
}

// ---------------------------------------------------------------------------
extern "C" void kernel_launch(void* const* d_in, const int* in_sizes, int n_in,
                              void* d_out, int out_size)
{
    const float* x    = (const float*)d_in[0];
    const float* edge = (const float*)d_in[1];
    const float* Wq   = (const float*)d_in[2];
    const float* Wk   = (const float*)d_in[3];
    const float* Wv   = (const float*)d_in[4];
    const float* Wo   = (const float*)d_in[5];
    const float* bo   = (const float*)d_in[6];
    float* out = (float*)d_out;

    // QKV projection
    qkv_kernel<<<dim3(15, 128), 256>>>(x, Wq, Wk, Wv);

    // flash attention (needs >48KB dyn smem)
    const int smem_bytes = (4*64*68 + 5*64) * (int)sizeof(float); // 70912
    cudaFuncSetAttribute(attn_kernel,
                         cudaFuncAttributeMaxDynamicSharedMemorySize, smem_bytes);
    attn_kernel<<<dim3(32, GG), 256, smem_bytes>>>(edge);

    // output projection
    oproj_kernel<<<dim3(5, 128), 256>>>(Wo, bo, out);
}

// round 6
// speedup vs baseline: 2.4070x; 2.4070x over previous
#include <cuda_runtime.h>
#include <cuda_bf16.h>
#include <cstdint>

#define BB 4
#define NN 2048
#define CC 320
#define HH 5
#define DD 64
#define GG (BB*HH)      // 20
#define ROWS (BB*NN)    // 8192

// scratch (allocation-free rule: __device__ globals)
__device__ float g_q[GG*NN*DD];
__device__ float g_k[GG*NN*DD];
__device__ float g_v[GG*NN*DD];
__device__ float g_attn[GG*NN*DD];

// ============================ mma.sync helpers =============================
__device__ __forceinline__ uint32_t pack_bf16(float a, float b) {
    __nv_bfloat162 t = __floats2bfloat162_rn(a, b);   // x=a (low), y=b (high)
    return *(uint32_t*)&t;
}

__device__ __forceinline__ void mma_bf16(float* d,
    uint32_t a0, uint32_t a1, uint32_t a2, uint32_t a3,
    uint32_t b0, uint32_t b1)
{
    asm volatile(
        "mma.sync.aligned.m16n8k16.row.col.f32.bf16.bf16.f32 "
        "{%0,%1,%2,%3}, {%4,%5,%6,%7}, {%8,%9}, {%0,%1,%2,%3};"
        : "+f"(d[0]), "+f"(d[1]), "+f"(d[2]), "+f"(d[3])
        : "r"(a0), "r"(a1), "r"(a2), "r"(a3), "r"(b0), "r"(b1));
}

// split float into bf16 hi + bf16 lo (residual)
__device__ __forceinline__ void bf16_split(float v, __nv_bfloat16& h, __nv_bfloat16& l) {
    h = __float2bfloat16(v);
    l = __float2bfloat16(v - __bfloat162float(h));
}

// ---------------------------------------------------------------------------
// Kernel 1: fused QKV projection (fp32, known-good).
// ---------------------------------------------------------------------------
__global__ void qkv_kernel(const float* __restrict__ x,
                           const float* __restrict__ Wq,
                           const float* __restrict__ Wk,
                           const float* __restrict__ Wv)
{
    __shared__ float As[16][68];
    __shared__ float Bs[16][68];

    const int tid = threadIdx.x;
    const int tx = tid & 15, ty = tid >> 4;
    const int row0 = blockIdx.y * 64;
    const int colt = blockIdx.x;
    const int w = colt / 5;
    const int h = colt % 5;
    const int wc0 = h * 64;
    const float* __restrict__ W = (w == 0) ? Wq : (w == 1) ? Wk : Wv;

    float acc[4][4] = {};

    for (int k0 = 0; k0 < CC; k0 += 16) {
        {
            int kk = tid & 15, r = tid >> 4;
            #pragma unroll
            for (int i = 0; i < 4; i++)
                As[kk][r + 16*i] = x[(row0 + r + 16*i)*CC + k0 + kk];
        }
        {
            int c = tid & 63, kk = tid >> 6;
            #pragma unroll
            for (int i = 0; i < 4; i++)
                Bs[kk + 4*i][c] = W[(k0 + kk + 4*i)*CC + wc0 + c];
        }
        __syncthreads();

        #pragma unroll
        for (int kk = 0; kk < 16; kk++) {
            float4 av = *(const float4*)&As[kk][ty*4];
            float4 bv = *(const float4*)&Bs[kk][tx*4];
            float a[4] = {av.x, av.y, av.z, av.w};
            float b[4] = {bv.x, bv.y, bv.z, bv.w};
            #pragma unroll
            for (int i = 0; i < 4; i++)
                #pragma unroll
                for (int j = 0; j < 4; j++)
                    acc[i][j] += a[i] * b[j];
        }
        __syncthreads();
    }

    float* __restrict__ dst = (w == 0) ? g_q : (w == 1) ? g_k : g_v;
    #pragma unroll
    for (int i = 0; i < 4; i++) {
        int row = row0 + ty*4 + i;
        int b = row / NN, n = row % NN;
        float4 o = make_float4(acc[i][0], acc[i][1], acc[i][2], acc[i][3]);
        *(float4*)&dst[((b*HH + h)*NN + n)*DD + tx*4] = o;
    }
}

// ---------------------------------------------------------------------------
// Kernel 2: mma.sync flash attention, full hi/lo bf16 compensation.
//   S = Qh·Kh + Qh·Kl + Ql·Kh (bf16, err ~2^-18)
//   P = exp(S) in regs (edge folded into Q,K; logits bounded -> bare exp)
//   O += Ph·Vh + Ph·Vl + Pl·Vh
//   CTA: 256 thr (8 warps), i-tile 128 rows; warp w owns rows w*16..+16.
//   smem (halves): Qh/Ql [128][72], Kh/Kl [128][72], Vh/Vl [64][136].
// ---------------------------------------------------------------------------
#define QK_STRIDE_W 36          // words per row (72 halves; 64 data + pad)
#define V_STRIDE_W  68          // words per row (136 halves; 128 data + pad)
#define SM_QH 0
#define SM_QL (SM_QH + 128*QK_STRIDE_W)
#define SM_KH (SM_QL + 128*QK_STRIDE_W)
#define SM_KL (SM_KH + 128*QK_STRIDE_W)
#define SM_VH (SM_KL + 128*QK_STRIDE_W)
#define SM_VL (SM_VH + 64*V_STRIDE_W)
#define ATTN_SMEM ((SM_VL + 64*V_STRIDE_W) * 4)   // 108544 B

__global__ void __launch_bounds__(256, 1)
attn_mma_kernel(const float* __restrict__ edge)
{
    extern __shared__ uint32_t sm[];
    __nv_bfloat16* Qh = (__nv_bfloat16*)(sm + SM_QH);
    __nv_bfloat16* Ql = (__nv_bfloat16*)(sm + SM_QL);
    __nv_bfloat16* Kh = (__nv_bfloat16*)(sm + SM_KH);
    __nv_bfloat16* Kl = (__nv_bfloat16*)(sm + SM_KL);
    __nv_bfloat16* Vh = (__nv_bfloat16*)(sm + SM_VH);
    __nv_bfloat16* Vl = (__nv_bfloat16*)(sm + SM_VL);
    uint32_t* QhW = sm + SM_QH;  uint32_t* QlW = sm + SM_QL;
    uint32_t* KhW = sm + SM_KH;  uint32_t* KlW = sm + SM_KL;
    uint32_t* VhW = sm + SM_VH;  uint32_t* VlW = sm + SM_VL;

    const int tid  = threadIdx.x;
    const int w    = tid >> 5;
    const int lane = tid & 31;
    const int lq   = lane >> 2;      // groupID
    const int cq   = lane & 3;       // threadID in group
    const int g    = blockIdx.y;
    const int i0   = blockIdx.x * 128;
    const int eb   = g % BB;         // batch-minor edge tiling!
    const int rb   = w * 16;

    // ---- prologue: Q tile -> smem bf16 hi/lo, folded with 0.125*e_i ----
    for (int idx = tid; idx < 128*64; idx += 256) {
        int r = idx >> 6, d = idx & 63;
        float e = edge[eb*NN + i0 + r] * 0.125f;
        float v = g_q[(g*NN + i0 + r)*DD + d] * e;
        __nv_bfloat16 h, l; bf16_split(v, h, l);
        Qh[r*(2*QK_STRIDE_W) + d] = h;
        Ql[r*(2*QK_STRIDE_W) + d] = l;
    }

    float Oacc[8][4] = {};
    float lsum0 = 0.0f, lsum1 = 0.0f;

    for (int jt = 0; jt < 16; jt++) {
        const int j0 = jt * 128;
        __syncthreads();   // previous iteration's smem consumers done

        // ---- K tile (folded e_j) and V tile (transposed) -> bf16 hi/lo ----
        for (int idx = tid; idx < 128*64; idx += 256) {
            int j = idx >> 6, d = idx & 63;
            float e = edge[eb*NN + j0 + j];
            float vk = g_k[(g*NN + j0 + j)*DD + d] * e;
            __nv_bfloat16 h, l; bf16_split(vk, h, l);
            Kh[j*(2*QK_STRIDE_W) + d] = h;
            Kl[j*(2*QK_STRIDE_W) + d] = l;
            float vv = g_v[(g*NN + j0 + j)*DD + d];
            __nv_bfloat16 vh, vl; bf16_split(vv, vh, vl);
            Vh[d*(2*V_STRIDE_W) + j] = vh;
            Vl[d*(2*V_STRIDE_W) + j] = vl;
        }
        __syncthreads();

        // ---- S = Q K^T : bf16 hi/lo 3-chain, warp tile m16 x n128, k64 ----
        float S[16][4];
        #pragma unroll
        for (int nb = 0; nb < 16; nb++)
            #pragma unroll
            for (int i = 0; i < 4; i++) S[nb][i] = 0.0f;

        #pragma unroll
        for (int kc = 0; kc < 4; kc++) {         // k-steps of 16
            const int wi = kc*8 + cq;            // word index within row
            uint32_t ah0 = QhW[(rb + lq    )*QK_STRIDE_W + wi];
            uint32_t ah1 = QhW[(rb + lq + 8)*QK_STRIDE_W + wi];
            uint32_t ah2 = QhW[(rb + lq    )*QK_STRIDE_W + wi + 4];
            uint32_t ah3 = QhW[(rb + lq + 8)*QK_STRIDE_W + wi + 4];
            uint32_t al0 = QlW[(rb + lq    )*QK_STRIDE_W + wi];
            uint32_t al1 = QlW[(rb + lq + 8)*QK_STRIDE_W + wi];
            uint32_t al2 = QlW[(rb + lq    )*QK_STRIDE_W + wi + 4];
            uint32_t al3 = QlW[(rb + lq + 8)*QK_STRIDE_W + wi + 4];
            #pragma unroll
            for (int nb = 0; nb < 16; nb++) {
                uint32_t bh0 = KhW[(nb*8 + lq)*QK_STRIDE_W + wi];
                uint32_t bh1 = KhW[(nb*8 + lq)*QK_STRIDE_W + wi + 4];
                uint32_t bl0 = KlW[(nb*8 + lq)*QK_STRIDE_W + wi];
                uint32_t bl1 = KlW[(nb*8 + lq)*QK_STRIDE_W + wi + 4];
                mma_bf16(S[nb], ah0, ah1, ah2, ah3, bh0, bh1);
                mma_bf16(S[nb], ah0, ah1, ah2, ah3, bl0, bl1);
                mma_bf16(S[nb], al0, al1, al2, al3, bh0, bh1);
            }
        }

        // ---- softmax (no max needed): p = exp(s); row sums ----
        #pragma unroll
        for (int nb = 0; nb < 16; nb++) {
            float p0 = __expf(S[nb][0]);
            float p1 = __expf(S[nb][1]);
            float p2 = __expf(S[nb][2]);
            float p3 = __expf(S[nb][3]);
            S[nb][0] = p0; S[nb][1] = p1; S[nb][2] = p2; S[nb][3] = p3;
            lsum0 += p0 + p1;
            lsum1 += p2 + p3;
        }

        // ---- O += P V : hi/lo 3-chain, P straight from regs ----
        #pragma unroll
        for (int kc = 0; kc < 8; kc++) {
            float p00 = S[2*kc][0],   p01 = S[2*kc][1];
            float p02 = S[2*kc][2],   p03 = S[2*kc][3];
            float p10 = S[2*kc+1][0], p11 = S[2*kc+1][1];
            float p12 = S[2*kc+1][2], p13 = S[2*kc+1][3];
            uint32_t ah0 = pack_bf16(p00, p01);
            uint32_t ah1 = pack_bf16(p02, p03);
            uint32_t ah2 = pack_bf16(p10, p11);
            uint32_t ah3 = pack_bf16(p12, p13);
            __nv_bfloat162 h0 = *(__nv_bfloat162*)&ah0;
            __nv_bfloat162 h1 = *(__nv_bfloat162*)&ah1;
            __nv_bfloat162 h2 = *(__nv_bfloat162*)&ah2;
            __nv_bfloat162 h3 = *(__nv_bfloat162*)&ah3;
            uint32_t al0 = pack_bf16(p00 - __bfloat162float(h0.x),
                                     p01 - __bfloat162float(h0.y));
            uint32_t al1 = pack_bf16(p02 - __bfloat162float(h1.x),
                                     p03 - __bfloat162float(h1.y));
            uint32_t al2 = pack_bf16(p10 - __bfloat162float(h2.x),
                                     p11 - __bfloat162float(h2.y));
            uint32_t al3 = pack_bf16(p12 - __bfloat162float(h3.x),
                                     p13 - __bfloat162float(h3.y));
            const int wi = kc*8 + cq;
            #pragma unroll
            for (int nd = 0; nd < 8; nd++) {
                uint32_t bh0 = VhW[(nd*8 + lq)*V_STRIDE_W + wi];
                uint32_t bh1 = VhW[(nd*8 + lq)*V_STRIDE_W + wi + 4];
                uint32_t bl0 = VlW[(nd*8 + lq)*V_STRIDE_W + wi];
                uint32_t bl1 = VlW[(nd*8 + lq)*V_STRIDE_W + wi + 4];
                mma_bf16(Oacc[nd], ah0, ah1, ah2, ah3, bh0, bh1);
                mma_bf16(Oacc[nd], ah0, ah1, ah2, ah3, bl0, bl1);
                mma_bf16(Oacc[nd], al0, al1, al2, al3, bh0, bh1);
            }
        }
    }

    // ---- reduce row sums across the quad that shares each row ----
    lsum0 += __shfl_xor_sync(0xFFFFFFFF, lsum0, 1);
    lsum0 += __shfl_xor_sync(0xFFFFFFFF, lsum0, 2);
    lsum1 += __shfl_xor_sync(0xFFFFFFFF, lsum1, 1);
    lsum1 += __shfl_xor_sync(0xFFFFFFFF, lsum1, 2);
    const float inv0 = 1.0f / lsum0;
    const float inv1 = 1.0f / lsum1;

    // ---- write O ----
    const int row0 = i0 + rb + lq;
    const int row1 = row0 + 8;
    float* __restrict__ dst0 = &g_attn[(g*NN + row0)*DD];
    float* __restrict__ dst1 = &g_attn[(g*NN + row1)*DD];
    #pragma unroll
    for (int nd = 0; nd < 8; nd++) {
        int col = nd*8 + 2*cq;
        *(float2*)&dst0[col] = make_float2(Oacc[nd][0]*inv0, Oacc[nd][1]*inv0);
        *(float2*)&dst1[col] = make_float2(Oacc[nd][2]*inv1, Oacc[nd][3]*inv1);
    }
}

// ---------------------------------------------------------------------------
// Kernel 3: output projection (fp32, known-good).
// ---------------------------------------------------------------------------
__global__ void oproj_kernel(const float* __restrict__ Wo,
                             const float* __restrict__ bo,
                             float* __restrict__ out)
{
    __shared__ float As[16][68];
    __shared__ float Bs[16][68];

    const int tid = threadIdx.x;
    const int tx = tid & 15, ty = tid >> 4;
    const int row0 = blockIdx.y * 64;
    const int c0 = blockIdx.x * 64;

    float acc[4][4] = {};

    for (int k0 = 0; k0 < CC; k0 += 16) {
        {
            int kk = tid & 15, r = tid >> 4;
            int k = k0 + kk;
            int h = k >> 6, d = k & 63;
            #pragma unroll
            for (int i = 0; i < 4; i++) {
                int row = row0 + r + 16*i;
                int b = row / NN, n = row % NN;
                As[kk][r + 16*i] = g_attn[((b*HH + h)*NN + n)*DD + d];
            }
        }
        {
            int c = tid & 63, kk = tid >> 6;
            #pragma unroll
            for (int i = 0; i < 4; i++)
                Bs[kk + 4*i][c] = Wo[(k0 + kk + 4*i)*CC + c0 + c];
        }
        __syncthreads();

        #pragma unroll
        for (int kk = 0; kk < 16; kk++) {
            float4 av = *(const float4*)&As[kk][ty*4];
            float4 bv = *(const float4*)&Bs[kk][tx*4];
            float a[4] = {av.x, av.y, av.z, av.w};
            float b[4] = {bv.x, bv.y, bv.z, bv.w};
            #pragma unroll
            for (int i = 0; i < 4; i++)
                #pragma unroll
                for (int j = 0; j < 4; j++)
                    acc[i][j] += a[i] * b[j];
        }
        __syncthreads();
    }

    #pragma unroll
    for (int i = 0; i < 4; i++) {
        int row = row0 + ty*4 + i;
        float4 bv = *(const float4*)&bo[c0 + tx*4];
        float4 o = make_float4(acc[i][0] + bv.x, acc[i][1] + bv.y,
                               acc[i][2] + bv.z, acc[i][3] + bv.w);
        *(float4*)&out[row*CC + c0 + tx*4] = o;
    }
}

// ---------------------------------------------------------------------------
extern "C" void kernel_launch(void* const* d_in, const int* in_sizes, int n_in,
                              void* d_out, int out_size)
{
    const float* x    = (const float*)d_in[0];
    const float* edge = (const float*)d_in[1];
    const float* Wq   = (const float*)d_in[2];
    const float* Wk   = (const float*)d_in[3];
    const float* Wv   = (const float*)d_in[4];
    const float* Wo   = (const float*)d_in[5];
    const float* bo   = (const float*)d_in[6];
    float* out = (float*)d_out;

    qkv_kernel<<<dim3(15, 128), 256>>>(x, Wq, Wk, Wv);

    cudaFuncSetAttribute(attn_mma_kernel,
                         cudaFuncAttributeMaxDynamicSharedMemorySize, ATTN_SMEM);
    attn_mma_kernel<<<dim3(16, GG), 256, ATTN_SMEM>>>(edge);

    oproj_kernel<<<dim3(5, 128), 256>>>(Wo, bo, out);
}

// round 7
// speedup vs baseline: 3.1320x; 1.3012x over previous
#include <cuda_runtime.h>
#include <cuda_bf16.h>
#include <cstdint>

#define BB 4
#define NN 2048
#define CC 320
#define HH 5
#define DD 64
#define GG (BB*HH)      // 20
#define ROWS (BB*NN)    // 8192

// scratch (allocation-free rule: __device__ globals)
__device__ __nv_bfloat16 g_qh[GG*NN*DD];   // folded 0.125*e_i, hi
__device__ __nv_bfloat16 g_ql[GG*NN*DD];   // lo
__device__ __nv_bfloat16 g_kh[GG*NN*DD];   // folded e_j, hi
__device__ __nv_bfloat16 g_kl[GG*NN*DD];   // lo
__device__ float         g_v [GG*NN*DD];   // fp32 (pre-transpose)
__device__ __nv_bfloat16 g_vth[GG*DD*NN];  // transposed (g,d,n), hi
__device__ __nv_bfloat16 g_vtl[GG*DD*NN];  // lo
__device__ float         g_attn[GG*NN*DD];

// ============================ helpers ======================================
__device__ __forceinline__ void mma_bf16(float* d,
    uint32_t a0, uint32_t a1, uint32_t a2, uint32_t a3,
    uint32_t b0, uint32_t b1)
{
    asm volatile(
        "mma.sync.aligned.m16n8k16.row.col.f32.bf16.bf16.f32 "
        "{%0,%1,%2,%3}, {%4,%5,%6,%7}, {%8,%9}, {%0,%1,%2,%3};"
        : "+f"(d[0]), "+f"(d[1]), "+f"(d[2]), "+f"(d[3])
        : "r"(a0), "r"(a1), "r"(a2), "r"(a3), "r"(b0), "r"(b1));
}

__device__ __forceinline__ void bf16_split(float v, __nv_bfloat16& h, __nv_bfloat16& l) {
    h = __float2bfloat16(v);
    l = __float2bfloat16(v - __bfloat162float(h));
}

__device__ __forceinline__ uint32_t pack_bf16(float a, float b) {
    __nv_bfloat162 t = __floats2bfloat162_rn(a, b);
    return *(uint32_t*)&t;
}

__device__ __forceinline__ uint32_t smem_u32(const void* p) {
    uint32_t a;
    asm("{ .reg .u64 t; cvta.to.shared.u64 t, %1; cvt.u32.u64 %0, t; }"
        : "=r"(a) : "l"(p));
    return a;
}

__device__ __forceinline__ void cp16(uint32_t dst, const void* src) {
    asm volatile("cp.async.cg.shared.global [%0], [%1], 16;"
                 :: "r"(dst), "l"(src) : "memory");
}
#define CP_COMMIT() asm volatile("cp.async.commit_group;" ::: "memory")
#define CP_WAIT0()  asm volatile("cp.async.wait_group 0;" ::: "memory")

// ---------------------------------------------------------------------------
// Kernel 1: QKV projection via bf16 hi/lo 3-chain MMA.
// CTA: 256 thr (8 warps), tile 128 rows x 64 cols (one of q/k/v x one head).
// Outputs: Q -> g_qh/g_ql folded with 0.125*e, K -> g_kh/g_kl folded with e,
//          V -> g_v fp32.  (edge batch for g=(b,h) is g%B -- batch-minor!)
// ---------------------------------------------------------------------------
#define X_STRIDE_W 20      // words per row (40 halves: 32 data + 8 pad)
__global__ void __launch_bounds__(256)
qkv_mma_kernel(const float* __restrict__ x,
               const float* __restrict__ Wq,
               const float* __restrict__ Wk,
               const float* __restrict__ Wv,
               const float* __restrict__ edge)
{
    __shared__ uint32_t smq[128*X_STRIDE_W*2 + 64*X_STRIDE_W*2];
    uint32_t* XhW = smq;
    uint32_t* XlW = XhW + 128*X_STRIDE_W;
    uint32_t* WhW = XlW + 128*X_STRIDE_W;
    uint32_t* WlW = WhW + 64*X_STRIDE_W;
    __nv_bfloat16* Xh = (__nv_bfloat16*)XhW;
    __nv_bfloat16* Xl = (__nv_bfloat16*)XlW;
    __nv_bfloat16* Wh = (__nv_bfloat16*)WhW;
    __nv_bfloat16* Wl = (__nv_bfloat16*)WlW;

    const int tid  = threadIdx.x;
    const int wid  = tid >> 5;
    const int lane = tid & 31;
    const int lq   = lane >> 2;
    const int cq   = lane & 3;
    const int rb   = wid * 16;
    const int colt = blockIdx.x;       // 0..14
    const int ot   = colt / 5;         // 0=q 1=k 2=v
    const int h    = colt % 5;
    const int wc0  = h * 64;
    const int row0 = blockIdx.y * 128;
    const float* __restrict__ W = (ot == 0) ? Wq : (ot == 1) ? Wk : Wv;

    float acc[8][4] = {};

    for (int k0 = 0; k0 < CC; k0 += 32) {
        __syncthreads();
        // X tile: 128 rows x 32 k, hi/lo split, k-contiguous rows
        #pragma unroll
        for (int i = 0; i < 16; i++) {
            int e = tid + 256*i;
            int kk = e & 31, r = e >> 5;
            float v = x[(row0 + r)*CC + k0 + kk];
            __nv_bfloat16 hh, ll; bf16_split(v, hh, ll);
            Xh[r*40 + kk] = hh;
            Xl[r*40 + kk] = ll;
        }
        // W tile: stored as [n][kk] (B^T layout, k-contiguous rows)
        #pragma unroll
        for (int i = 0; i < 8; i++) {
            int e = tid + 256*i;
            int n = e & 63, kk = e >> 6;
            float v = W[(k0 + kk)*CC + wc0 + n];
            __nv_bfloat16 hh, ll; bf16_split(v, hh, ll);
            Wh[n*40 + kk] = hh;
            Wl[n*40 + kk] = ll;
        }
        __syncthreads();

        #pragma unroll
        for (int kc = 0; kc < 2; kc++) {
            const int wi = kc*8 + cq;
            uint32_t ah0 = XhW[(rb + lq    )*X_STRIDE_W + wi];
            uint32_t ah1 = XhW[(rb + lq + 8)*X_STRIDE_W + wi];
            uint32_t ah2 = XhW[(rb + lq    )*X_STRIDE_W + wi + 4];
            uint32_t ah3 = XhW[(rb + lq + 8)*X_STRIDE_W + wi + 4];
            uint32_t al0 = XlW[(rb + lq    )*X_STRIDE_W + wi];
            uint32_t al1 = XlW[(rb + lq + 8)*X_STRIDE_W + wi];
            uint32_t al2 = XlW[(rb + lq    )*X_STRIDE_W + wi + 4];
            uint32_t al3 = XlW[(rb + lq + 8)*X_STRIDE_W + wi + 4];
            #pragma unroll
            for (int nb = 0; nb < 8; nb++) {
                uint32_t bh0 = WhW[(nb*8 + lq)*X_STRIDE_W + wi];
                uint32_t bh1 = WhW[(nb*8 + lq)*X_STRIDE_W + wi + 4];
                uint32_t bl0 = WlW[(nb*8 + lq)*X_STRIDE_W + wi];
                uint32_t bl1 = WlW[(nb*8 + lq)*X_STRIDE_W + wi + 4];
                mma_bf16(acc[nb], ah0, ah1, ah2, ah3, bh0, bh1);
                mma_bf16(acc[nb], ah0, ah1, ah2, ah3, bl0, bl1);
                mma_bf16(acc[nb], al0, al1, al2, al3, bh0, bh1);
            }
        }
    }

    // ---- epilogue ----
    const int r0 = row0 + rb + lq;
    const int b  = r0 >> 11;
    const int n0 = r0 & 2047;
    const int n1 = n0 + 8;
    const int g  = b*HH + h;
    const size_t base0 = ((size_t)g*NN + n0)*DD;
    const size_t base1 = ((size_t)g*NN + n1)*DD;

    if (ot == 2) {
        #pragma unroll
        for (int nb = 0; nb < 8; nb++) {
            int col = nb*8 + 2*cq;
            *(float2*)&g_v[base0 + col] = make_float2(acc[nb][0], acc[nb][1]);
            *(float2*)&g_v[base1 + col] = make_float2(acc[nb][2], acc[nb][3]);
        }
    } else {
        const int eb = g & 3;                        // g % B  (batch-minor!)
        const float s  = (ot == 0) ? 0.125f : 1.0f;
        const float f0 = edge[eb*NN + n0] * s;
        const float f1 = edge[eb*NN + n1] * s;
        __nv_bfloat16* __restrict__ dh = (ot == 0) ? g_qh : g_kh;
        __nv_bfloat16* __restrict__ dl = (ot == 0) ? g_ql : g_kl;
        #pragma unroll
        for (int nb = 0; nb < 8; nb++) {
            int col = nb*8 + 2*cq;
            float v00 = acc[nb][0]*f0, v01 = acc[nb][1]*f0;
            float v10 = acc[nb][2]*f1, v11 = acc[nb][3]*f1;
            __nv_bfloat16 h00, l00, h01, l01, h10, l10, h11, l11;
            bf16_split(v00, h00, l00); bf16_split(v01, h01, l01);
            bf16_split(v10, h10, l10); bf16_split(v11, h11, l11);
            __nv_bfloat162 t;
            t.x = h00; t.y = h01; *(__nv_bfloat162*)&dh[base0 + col] = t;
            t.x = l00; t.y = l01; *(__nv_bfloat162*)&dl[base0 + col] = t;
            t.x = h10; t.y = h11; *(__nv_bfloat162*)&dh[base1 + col] = t;
            t.x = l10; t.y = l11; *(__nv_bfloat162*)&dl[base1 + col] = t;
        }
    }
}

// ---------------------------------------------------------------------------
// Kernel 1b: V transpose + bf16 hi/lo split:  (g,n,d) f32 -> (g,d,n) bf16 x2.
// ---------------------------------------------------------------------------
__global__ void __launch_bounds__(256)
vtrans_kernel()
{
    __shared__ float T[64][65];
    const int tid = threadIdx.x;
    const int nt  = blockIdx.x;      // n-tile of 64
    const int g   = blockIdx.y;

    #pragma unroll
    for (int i = 0; i < 16; i++) {
        int e = tid + 256*i;
        int d = e & 63, n = e >> 6;
        T[n][d] = g_v[((size_t)g*NN + nt*64 + n)*DD + d];
    }
    __syncthreads();
    #pragma unroll
    for (int i = 0; i < 8; i++) {
        int e = tid + 256*i;
        int np = e & 31, d = e >> 5;
        int n = 2*np;
        float v0 = T[n][d], v1 = T[n+1][d];
        __nv_bfloat16 h0, l0, h1, l1;
        bf16_split(v0, h0, l0); bf16_split(v1, h1, l1);
        size_t o = ((size_t)g*DD + d)*NN + nt*64 + n;
        __nv_bfloat162 t;
        t.x = h0; t.y = h1; *(__nv_bfloat162*)&g_vth[o] = t;
        t.x = l0; t.y = l1; *(__nv_bfloat162*)&g_vtl[o] = t;
    }
}

// ---------------------------------------------------------------------------
// Kernel 2: mma.sync flash attention, full hi/lo bf16 compensation.
// Inputs are pre-folded, pre-split bf16 -> fills are pure cp.async copies.
// 2 CTAs/SM (108.5 KB smem each) for inter-CTA load/compute overlap.
// ---------------------------------------------------------------------------
#define QK_STRIDE_W 36          // words per row (144 B: 128 data + 16 pad)
#define V_STRIDE_W  68          // words per row (272 B: 256 data + 16 pad)
#define QH_B 0
#define QL_B 18432
#define KH_B 36864
#define KL_B 55296
#define VH_B 73728
#define VL_B 91136
#define ATTN_SMEM 108544

__global__ void __launch_bounds__(256, 2)
attn_mma_kernel()
{
    extern __shared__ char smx[];
    const uint32_t sb = smem_u32(smx);
    uint32_t* QhW = (uint32_t*)(smx + QH_B);
    uint32_t* QlW = (uint32_t*)(smx + QL_B);
    uint32_t* KhW = (uint32_t*)(smx + KH_B);
    uint32_t* KlW = (uint32_t*)(smx + KL_B);
    uint32_t* VhW = (uint32_t*)(smx + VH_B);
    uint32_t* VlW = (uint32_t*)(smx + VL_B);

    const int tid  = threadIdx.x;
    const int w    = tid >> 5;
    const int lane = tid & 31;
    const int lq   = lane >> 2;
    const int cq   = lane & 3;
    const int g    = blockIdx.y;
    const int i0   = blockIdx.x * 128;
    const int rb   = w * 16;

    // ---- prologue: Q tile via cp.async (pre-folded bf16 hi/lo) ----
    #pragma unroll
    for (int i = 0; i < 4; i++) {
        int c = tid + 256*i;                 // 1024 chunks each
        int r = c >> 3, cc = c & 7;
        cp16(sb + QH_B + r*144 + cc*16, g_qh + ((size_t)g*NN + i0 + r)*DD + cc*8);
        cp16(sb + QL_B + r*144 + cc*16, g_ql + ((size_t)g*NN + i0 + r)*DD + cc*8);
    }
    CP_COMMIT();

    float Oacc[8][4] = {};
    float lsum0 = 0.0f, lsum1 = 0.0f;

    for (int jt = 0; jt < 16; jt++) {
        const int j0 = jt * 128;
        __syncthreads();   // previous tile's consumers done

        // ---- K and V tiles via cp.async ----
        #pragma unroll
        for (int i = 0; i < 4; i++) {
            int c = tid + 256*i;
            int j = c >> 3, cc = c & 7;
            cp16(sb + KH_B + j*144 + cc*16, g_kh + ((size_t)g*NN + j0 + j)*DD + cc*8);
            cp16(sb + KL_B + j*144 + cc*16, g_kl + ((size_t)g*NN + j0 + j)*DD + cc*8);
        }
        #pragma unroll
        for (int i = 0; i < 4; i++) {
            int c = tid + 256*i;
            int d = c >> 4, cc = c & 15;
            cp16(sb + VH_B + d*272 + cc*16, g_vth + ((size_t)g*DD + d)*NN + j0 + cc*8);
            cp16(sb + VL_B + d*272 + cc*16, g_vtl + ((size_t)g*DD + d)*NN + j0 + cc*8);
        }
        CP_COMMIT();
        CP_WAIT0();
        __syncthreads();

        // ---- S = Q K^T : bf16 hi/lo 3-chain, warp tile m16 x n128, k64 ----
        float S[16][4];
        #pragma unroll
        for (int nb = 0; nb < 16; nb++)
            #pragma unroll
            for (int i = 0; i < 4; i++) S[nb][i] = 0.0f;

        #pragma unroll
        for (int kc = 0; kc < 4; kc++) {
            const int wi = kc*8 + cq;
            uint32_t ah0 = QhW[(rb + lq    )*QK_STRIDE_W + wi];
            uint32_t ah1 = QhW[(rb + lq + 8)*QK_STRIDE_W + wi];
            uint32_t ah2 = QhW[(rb + lq    )*QK_STRIDE_W + wi + 4];
            uint32_t ah3 = QhW[(rb + lq + 8)*QK_STRIDE_W + wi + 4];
            uint32_t al0 = QlW[(rb + lq    )*QK_STRIDE_W + wi];
            uint32_t al1 = QlW[(rb + lq + 8)*QK_STRIDE_W + wi];
            uint32_t al2 = QlW[(rb + lq    )*QK_STRIDE_W + wi + 4];
            uint32_t al3 = QlW[(rb + lq + 8)*QK_STRIDE_W + wi + 4];
            #pragma unroll
            for (int nb = 0; nb < 16; nb++) {
                uint32_t bh0 = KhW[(nb*8 + lq)*QK_STRIDE_W + wi];
                uint32_t bh1 = KhW[(nb*8 + lq)*QK_STRIDE_W + wi + 4];
                uint32_t bl0 = KlW[(nb*8 + lq)*QK_STRIDE_W + wi];
                uint32_t bl1 = KlW[(nb*8 + lq)*QK_STRIDE_W + wi + 4];
                mma_bf16(S[nb], ah0, ah1, ah2, ah3, bh0, bh1);
                mma_bf16(S[nb], ah0, ah1, ah2, ah3, bl0, bl1);
                mma_bf16(S[nb], al0, al1, al2, al3, bh0, bh1);
            }
        }

        // ---- softmax (logits bounded, no max needed) ----
        #pragma unroll
        for (int nb = 0; nb < 16; nb++) {
            float p0 = __expf(S[nb][0]);
            float p1 = __expf(S[nb][1]);
            float p2 = __expf(S[nb][2]);
            float p3 = __expf(S[nb][3]);
            S[nb][0] = p0; S[nb][1] = p1; S[nb][2] = p2; S[nb][3] = p3;
            lsum0 += p0 + p1;
            lsum1 += p2 + p3;
        }

        // ---- O += P V : hi/lo 3-chain, P straight from regs ----
        #pragma unroll
        for (int kc = 0; kc < 8; kc++) {
            float p00 = S[2*kc][0],   p01 = S[2*kc][1];
            float p02 = S[2*kc][2],   p03 = S[2*kc][3];
            float p10 = S[2*kc+1][0], p11 = S[2*kc+1][1];
            float p12 = S[2*kc+1][2], p13 = S[2*kc+1][3];
            uint32_t ah0 = pack_bf16(p00, p01);
            uint32_t ah1 = pack_bf16(p02, p03);
            uint32_t ah2 = pack_bf16(p10, p11);
            uint32_t ah3 = pack_bf16(p12, p13);
            __nv_bfloat162 h0 = *(__nv_bfloat162*)&ah0;
            __nv_bfloat162 h1 = *(__nv_bfloat162*)&ah1;
            __nv_bfloat162 h2 = *(__nv_bfloat162*)&ah2;
            __nv_bfloat162 h3 = *(__nv_bfloat162*)&ah3;
            uint32_t al0 = pack_bf16(p00 - __bfloat162float(h0.x),
                                     p01 - __bfloat162float(h0.y));
            uint32_t al1 = pack_bf16(p02 - __bfloat162float(h1.x),
                                     p03 - __bfloat162float(h1.y));
            uint32_t al2 = pack_bf16(p10 - __bfloat162float(h2.x),
                                     p11 - __bfloat162float(h2.y));
            uint32_t al3 = pack_bf16(p12 - __bfloat162float(h3.x),
                                     p13 - __bfloat162float(h3.y));
            const int wi = kc*8 + cq;
            #pragma unroll
            for (int nd = 0; nd < 8; nd++) {
                uint32_t bh0 = VhW[(nd*8 + lq)*V_STRIDE_W + wi];
                uint32_t bh1 = VhW[(nd*8 + lq)*V_STRIDE_W + wi + 4];
                uint32_t bl0 = VlW[(nd*8 + lq)*V_STRIDE_W + wi];
                uint32_t bl1 = VlW[(nd*8 + lq)*V_STRIDE_W + wi + 4];
                mma_bf16(Oacc[nd], ah0, ah1, ah2, ah3, bh0, bh1);
                mma_bf16(Oacc[nd], ah0, ah1, ah2, ah3, bl0, bl1);
                mma_bf16(Oacc[nd], al0, al1, al2, al3, bh0, bh1);
            }
        }
    }

    // ---- reduce row sums across the quad sharing each row ----
    lsum0 += __shfl_xor_sync(0xFFFFFFFF, lsum0, 1);
    lsum0 += __shfl_xor_sync(0xFFFFFFFF, lsum0, 2);
    lsum1 += __shfl_xor_sync(0xFFFFFFFF, lsum1, 1);
    lsum1 += __shfl_xor_sync(0xFFFFFFFF, lsum1, 2);
    const float inv0 = 1.0f / lsum0;
    const float inv1 = 1.0f / lsum1;

    const int row0 = i0 + rb + lq;
    const int row1 = row0 + 8;
    float* __restrict__ dst0 = &g_attn[((size_t)g*NN + row0)*DD];
    float* __restrict__ dst1 = &g_attn[((size_t)g*NN + row1)*DD];
    #pragma unroll
    for (int nd = 0; nd < 8; nd++) {
        int col = nd*8 + 2*cq;
        *(float2*)&dst0[col] = make_float2(Oacc[nd][0]*inv0, Oacc[nd][1]*inv0);
        *(float2*)&dst1[col] = make_float2(Oacc[nd][2]*inv1, Oacc[nd][3]*inv1);
    }
}

// ---------------------------------------------------------------------------
// Kernel 3: output projection (fp32, known-good).
// ---------------------------------------------------------------------------
__global__ void oproj_kernel(const float* __restrict__ Wo,
                             const float* __restrict__ bo,
                             float* __restrict__ out)
{
    __shared__ float As[16][68];
    __shared__ float Bs[16][68];

    const int tid = threadIdx.x;
    const int tx = tid & 15, ty = tid >> 4;
    const int row0 = blockIdx.y * 64;
    const int c0 = blockIdx.x * 64;

    float acc[4][4] = {};

    for (int k0 = 0; k0 < CC; k0 += 16) {
        {
            int kk = tid & 15, r = tid >> 4;
            int k = k0 + kk;
            int h = k >> 6, d = k & 63;
            #pragma unroll
            for (int i = 0; i < 4; i++) {
                int row = row0 + r + 16*i;
                int b = row / NN, n = row % NN;
                As[kk][r + 16*i] = g_attn[((size_t)(b*HH + h)*NN + n)*DD + d];
            }
        }
        {
            int c = tid & 63, kk = tid >> 6;
            #pragma unroll
            for (int i = 0; i < 4; i++)
                Bs[kk + 4*i][c] = Wo[(k0 + kk + 4*i)*CC + c0 + c];
        }
        __syncthreads();

        #pragma unroll
        for (int kk = 0; kk < 16; kk++) {
            float4 av = *(const float4*)&As[kk][ty*4];
            float4 bv = *(const float4*)&Bs[kk][tx*4];
            float a[4] = {av.x, av.y, av.z, av.w};
            float b[4] = {bv.x, bv.y, bv.z, bv.w};
            #pragma unroll
            for (int i = 0; i < 4; i++)
                #pragma unroll
                for (int j = 0; j < 4; j++)
                    acc[i][j] += a[i] * b[j];
        }
        __syncthreads();
    }

    #pragma unroll
    for (int i = 0; i < 4; i++) {
        int row = row0 + ty*4 + i;
        float4 bv = *(const float4*)&bo[c0 + tx*4];
        float4 o = make_float4(acc[i][0] + bv.x, acc[i][1] + bv.y,
                               acc[i][2] + bv.z, acc[i][3] + bv.w);
        *(float4*)&out[row*CC + c0 + tx*4] = o;
    }
}

// ---------------------------------------------------------------------------
extern "C" void kernel_launch(void* const* d_in, const int* in_sizes, int n_in,
                              void* d_out, int out_size)
{
    const float* x    = (const float*)d_in[0];
    const float* edge = (const float*)d_in[1];
    const float* Wq   = (const float*)d_in[2];
    const float* Wk   = (const float*)d_in[3];
    const float* Wv   = (const float*)d_in[4];
    const float* Wo   = (const float*)d_in[5];
    const float* bo   = (const float*)d_in[6];
    float* out = (float*)d_out;

    qkv_mma_kernel<<<dim3(15, 64), 256>>>(x, Wq, Wk, Wv, edge);
    vtrans_kernel<<<dim3(32, GG), 256>>>();

    cudaFuncSetAttribute(attn_mma_kernel,
                         cudaFuncAttributeMaxDynamicSharedMemorySize, ATTN_SMEM);
    attn_mma_kernel<<<dim3(16, GG), 256, ATTN_SMEM>>>();

    oproj_kernel<<<dim3(5, 128), 256>>>(Wo, bo, out);
}